// round 17
// baseline (speedup 1.0000x reference)
#include <cuda_runtime.h>

// ---------------- problem constants ----------------
#define NB    384          // proposals per image
#define NC    11           // classes incl background
#define NFG   10           // foreground classes
#define NIMG  2            // images
#define NGRP  (NIMG*NFG)   // 20 NMS groups
#define MTOT  (NIMG*NB)    // 768 proposals
#define DET   100
#define MASKW 12           // ceil(384/32)
#define EPSF  1e-8f
#define SCORE_TH 0.05f
#define NMS_TH   0.5f
#define XFORM_CLIP 4.135166556742356f   // log(1000/16)
#define FULLM 0xFFFFFFFFu
#define SUBB  37           // pair-kernel blocks per group
#define QMAX  2048         // max pairs per block
#define CKMAX 4096         // per-image candidate key buffer (>= NFG*NB)
#define CANDC 512          // post-refine candidate cap

// ---------------- device scratch (no allocs allowed) ----------------
__device__ float    g_boxes [NGRP*NB*5];
__device__ int      g_vcnt  [NGRP];
__device__ int      g_vlist [NGRP*NB];
__device__ float    g_psc   [NGRP*NB];
__device__ float4   g_pcorn4[NGRP*NB*2];   // corners as 2x float4 (sorted order)
__device__ float4   g_pmeta [NGRP*NB];     // (cx, cy, area, rad)  (sorted order)
__device__ unsigned g_mask  [NGRP*NB*MASKW];
__device__ unsigned long long g_ckeys[NIMG*CKMAX];  // kept keys per image (unordered)
__device__ int      g_ccnt  [NIMG];

// ---------------- kernel 1: fused decode + softmax + sort + permute ----------------
__global__ void __launch_bounds__(512) k_decsort(const float* __restrict__ logits,
                                                 const float* __restrict__ reg,
                                                 const float* __restrict__ rr)
{
    __shared__ unsigned long long skeys[512];
    __shared__ float scorn[NB*8];
    __shared__ float4 smeta[NB];

    int g = blockIdx.x;
    int t = threadIdx.x;
    int b = g / NFG, cf = g % NFG, c = cf + 1;

    if (t == 0 && g < NIMG) g_ccnt[g] = 0;   // reset each graph replay (runs before k_greedy)

    bool val = false;
    unsigned long long key;
    if (t < NB){
        int m = b*NB + t;
        float mx = -1e30f;
        float l[NC];
        #pragma unroll
        for (int k=0;k<NC;k++){ l[k] = __ldg(&logits[m*NC+k]); mx = fmaxf(mx, l[k]); }
        float s = 0.f;
        #pragma unroll
        for (int k=0;k<NC;k++) s += expf(l[k]-mx);
        float prob = expf(l[c]-mx)/s;

        float xc = __ldg(&rr[m*5+0]), yc = __ldg(&rr[m*5+1]);
        float w  = __ldg(&rr[m*5+2]), h  = __ldg(&rr[m*5+3]), a = __ldg(&rr[m*5+4]);

        const float* r = &reg[m*(NC*5) + c*5];
        float dx = __ldg(&r[0])/10.0f;
        float dy = __ldg(&r[1])/10.0f;
        float dw = fminf(__ldg(&r[2])/5.0f, XFORM_CLIP);
        float dh = fminf(__ldg(&r[3])/5.0f, XFORM_CLIP);
        float da = __ldg(&r[4]);

        float px = dx*w + xc;
        float py = dy*h + yc;
        float pw = expf(dw)*w;
        float ph = expf(dh)*h;
        float pa = da*(float)(180.0/3.14159265358979323846) + a;
        float x2 = pa + 180.0f;
        float rm = fmodf(x2, 360.0f);
        if (rm < 0.0f) rm += 360.0f;
        pa = rm - 180.0f;

        int o = g*NB + t;
        g_boxes[o*5+0] = px; g_boxes[o*5+1] = py;
        g_boxes[o*5+2] = pw; g_boxes[o*5+3] = ph; g_boxes[o*5+4] = pa;

        smeta[t] = make_float4(px, py, pw*ph, 0.5f*sqrtf(pw*pw + ph*ph));

        float th = pa*(float)(3.14159265358979323846/180.0);
        float cs = cosf(th), sn = sinf(th);
        float hx = pw*0.5f, hy = ph*0.5f;
        float lx[4] = {-hx, hx, hx, -hx};
        float ly[4] = {-hy, -hy, hy, hy};
        #pragma unroll
        for (int k=0;k<4;k++){
            scorn[t*8+2*k]   = px + lx[k]*cs - ly[k]*sn;
            scorn[t*8+2*k+1] = py + lx[k]*sn + ly[k]*cs;
        }

        val = prob > SCORE_TH;
        float kf = val ? prob : __int_as_float(0xFF800000);
        unsigned ub = __float_as_uint(kf);
        ub = (ub & 0x80000000u) ? ~ub : (ub | 0x80000000u);
        key = (((unsigned long long)(~ub)) << 32) | (unsigned)t;
    } else {
        key = 0xFFFFFFFF00000000ull | (unsigned)t;
    }
    // zero this group's suppression mask (graph replays!)
    for (int w = t; w < NB*MASKW; w += 512) g_mask[g*NB*MASKW + w] = 0u;
    int vv = __syncthreads_count(val);
    if (t == 0) g_vcnt[g] = vv;

    // hybrid bitonic: shared for j>=32, shfl for j<32 (ascending == score desc)
    #pragma unroll
    for (int k=2;k<=512;k<<=1){
        #pragma unroll
        for (int j=k>>1;j>=32;j>>=1){
            skeys[t]=key; __syncthreads();
            unsigned long long o = skeys[t^j]; __syncthreads();
            bool up = ((t&k)==0), lower = ((t&j)==0);
            key = ((key<o)==(lower==up)) ? key : o;
        }
        int jmax = (k>>1) < 16 ? (k>>1) : 16;
        #pragma unroll
        for (int j=jmax;j>0;j>>=1){
            unsigned long long o = __shfl_xor_sync(FULLM, key, j);
            bool up = ((t&k)==0), lower = ((t&j)==0);
            key = ((key<o)==(lower==up)) ? key : o;
        }
    }

    // permute per-box data into sorted order (from shared)
    if (t < vv){
        int n = (int)(key & 0xFFFFFFFFull);
        unsigned ub = ~(unsigned)(key >> 32);
        unsigned bits = (ub & 0x80000000u) ? (ub ^ 0x80000000u) : ~ub;
        int q = g*NB + t;
        g_vlist[q] = n;
        g_psc[q]   = __uint_as_float(bits);
        const float* cp = &scorn[n*8];
        g_pcorn4[q*2+0] = make_float4(cp[0],cp[1],cp[2],cp[3]);
        g_pcorn4[q*2+1] = make_float4(cp[4],cp[5],cp[6],cp[7]);
        g_pmeta[q] = smeta[n];
    }
}

// ---------------- rotated-rect intersection: register-only, bitonic-32 network ----------------
__device__ __forceinline__ float crs(float ax,float ay,float bx,float by){
    return ax*by - ay*bx;
}

__device__ __forceinline__ float inter_area_reg(float4 ca0, float4 ca1,
                                                float4 cb0, float4 cb1)
{
    float ax[4] = {ca0.x, ca0.z, ca1.x, ca1.z};
    float ay[4] = {ca0.y, ca0.w, ca1.y, ca1.w};
    float bx4[4] = {cb0.x, cb0.z, cb1.x, cb1.z};
    float by4[4] = {cb0.y, cb0.w, cb1.y, cb1.w};
    float d1x[4],d1y[4],d2x[4],d2y[4];
    #pragma unroll
    for (int k=0;k<4;k++){
        d1x[k]=ax[(k+1)&3]-ax[k];  d1y[k]=ay[(k+1)&3]-ay[k];
        d2x[k]=bx4[(k+1)&3]-bx4[k]; d2y[k]=by4[(k+1)&3]-by4[k];
    }

    float px[24], py[24]; bool ok[24];
    #pragma unroll
    for (int i=0;i<4;i++){
        #pragma unroll
        for (int j=0;j<4;j++){
            float den  = crs(d1x[i],d1y[i],d2x[j],d2y[j]);
            float dfx  = bx4[j]-ax[i], dfy = by4[j]-ay[i];
            float dens = (fabsf(den) < EPSF) ? 1.0f : den;
            float t = crs(dfx,dfy,d2x[j],d2y[j]) / dens;
            float u = crs(dfx,dfy,d1x[i],d1y[i]) / dens;
            bool o = (fabsf(den) >= EPSF) && (t>=0.0f) && (t<=1.0f) && (u>=0.0f) && (u<=1.0f);
            px[4*i+j] = ax[i] + t*d1x[i];
            py[4*i+j] = ay[i] + t*d1y[i];
            ok[4*i+j] = o;
        }
    }
    #pragma unroll
    for (int p=0;p<4;p++){
        bool allpos=true, allneg=true;
        #pragma unroll
        for (int e=0;e<4;e++){
            float cr = crs(d2x[e],d2y[e], ax[p]-bx4[e], ay[p]-by4[e]);
            allpos = allpos && (cr >= -1e-6f);
            allneg = allneg && (cr <=  1e-6f);
        }
        ok[16+p] = allpos || allneg;
        px[16+p] = ax[p]; py[16+p] = ay[p];
    }
    #pragma unroll
    for (int p=0;p<4;p++){
        bool allpos=true, allneg=true;
        #pragma unroll
        for (int e=0;e<4;e++){
            float cr = crs(d1x[e],d1y[e], bx4[p]-ax[e], by4[p]-ay[e]);
            allpos = allpos && (cr >= -1e-6f);
            allneg = allneg && (cr <=  1e-6f);
        }
        ok[20+p] = allpos || allneg;
        px[20+p] = bx4[p]; py[20+p] = by4[p];
    }

    int nv = 0; float cx = 0.0f, cy = 0.0f;
    #pragma unroll
    for (int i=0;i<24;i++) if (ok[i]){ nv++; cx += px[i]; cy += py[i]; }
    if (nv < 3) return 0.0f;
    cx /= (float)nv;  cy /= (float)nv;

    // reference semantics: 24 points, invalid parked AT centroid with angle +0,
    // sorted by angle, shoelace over cyclic order. Ties occur only among
    // coordinate-identical centroid copies -> any order gives the same sum.
    unsigned kk[32];
    float sxp[32], syp[32];
    #pragma unroll
    for (int i=0;i<24;i++){
        bool o = ok[i];
        float x = o ? px[i] : cx;
        float y = o ? py[i] : cy;
        float a = o ? atan2f(y-cy, x-cx) : 0.0f;
        unsigned u = __float_as_uint(a);
        u = (u & 0x80000000u) ? ~u : (u | 0x80000000u);
        kk[i] = u; sxp[i] = x; syp[i] = y;
    }
    #pragma unroll
    for (int i=24;i<32;i++){ kk[i] = 0xFFFFFFFFu; sxp[i] = cx; syp[i] = cy; }

    #pragma unroll
    for (int k=2;k<=32;k<<=1){
        #pragma unroll
        for (int j=k>>1;j>0;j>>=1){
            #pragma unroll
            for (int ii=0;ii<32;ii++){
                int jj = ii ^ j;
                if (jj > ii){
                    bool up = ((ii & k) == 0);
                    bool sw = (kk[ii] > kk[jj]) == up;
                    unsigned ka=kk[ii], kb=kk[jj];
                    float xa=sxp[ii], xb=sxp[jj];
                    float ya=syp[ii], yb=syp[jj];
                    kk[ii]=sw?kb:ka;  kk[jj]=sw?ka:kb;
                    sxp[ii]=sw?xb:xa; sxp[jj]=sw?xa:xb;
                    syp[ii]=sw?yb:ya; syp[jj]=sw?ya:yb;
                }
            }
        }
    }
    float s = 0.0f;
    #pragma unroll
    for (int i=0;i<24;i++){
        int jn = (i+1) % 24;
        s += sxp[i]*syp[jn] - syp[i]*sxp[jn];
    }
    return 0.5f*fabsf(s);
}

// ---------------- kernel 2: prefilter -> queue -> full-warp clips ----------------
__global__ void __launch_bounds__(256) k_pairs()
{
    __shared__ int qcnt;
    __shared__ int queue[QMAX];

    int g   = blockIdx.x / SUBB;
    int sub = blockIdx.x % SUBB;
    int v = g_vcnt[g];
    int P = v*(v-1)/2;
    int base = g*NB;

    if (threadIdx.x == 0) qcnt = 0;
    __syncthreads();

    // phase 1: prefilters only; push survivors
    for (int p = sub*256 + threadIdx.x; p < P; p += SUBB*256){
        int j = (int)((1.0f + sqrtf(1.0f + 8.0f*(float)p))*0.5f);
        while (j*(j-1)/2 > p) j--;
        while ((j+1)*j/2 <= p) j++;
        int i = p - j*(j-1)/2;

        float4 mi = g_pmeta[base+i];
        float4 mj = g_pmeta[base+j];
        float aA = mi.z, aB = mj.z;
        float mn = fminf(aA,aB), sm = aA + aB;
        if (3.0f*mn <= sm*(1.0f - 1e-4f)) continue;      // IoU<=0.5 certain
        float dx = mi.x-mj.x, dy = mi.y-mj.y;
        float rr = mi.w+mj.w;
        if (dx*dx + dy*dy >= rr*rr) continue;            // disjoint
        int slot = atomicAdd(&qcnt, 1);
        if (slot < QMAX) queue[slot] = (i<<9) | j;
    }
    __syncthreads();
    int Q = qcnt < QMAX ? qcnt : QMAX;

    // phase 2: full warps do clips in lockstep (no divergence serialization)
    for (int q = threadIdx.x; q < Q; q += 256){
        int pk = queue[q];
        int i = pk >> 9, j = pk & 511;
        float4 ca0 = g_pcorn4[(base+i)*2+0], ca1 = g_pcorn4[(base+i)*2+1];
        float4 cb0 = g_pcorn4[(base+j)*2+0], cb1 = g_pcorn4[(base+j)*2+1];
        float inter = inter_area_reg(ca0, ca1, cb0, cb1);
        float aA = g_pmeta[base+i].z, aB = g_pmeta[base+j].z;
        float iou = inter / (aA + aB - inter + EPSF);
        if (iou > NMS_TH)
            atomicOr(&g_mask[(base+i)*MASKW + (j>>5)], 1u << (j&31));
    }
}

// ---------------- kernel 3: greedy -> compacted per-image kept keys ----------------
__global__ void __launch_bounds__(256) k_greedy()
{
    __shared__ unsigned sm[NB*MASKW];
    __shared__ unsigned sblk[MASKW];
    int g = blockIdx.x;
    int t = threadIdx.x;
    int v = g_vcnt[g];
    int bimg = g / NFG, cf = g % NFG;

    for (int w = t; w < v*MASKW; w += 256) sm[w] = g_mask[g*NB*MASKW + w];
    if (t < MASKW) sblk[t] = 0u;
    __syncthreads();

    int B = (v + 31) & ~31;
    for (int r0 = t; r0 < B; r0 += 256){
        bool any = false;
        if (r0 < v){
            unsigned o = 0u;
            #pragma unroll
            for (int w=0;w<MASKW;w++) o |= sm[r0*MASKW+w];
            any = (o != 0u);
        }
        unsigned bal = __ballot_sync(FULLM, any);
        if ((t & 31) == 0) sblk[r0 >> 5] = bal;
    }
    __syncthreads();

    if (t < 32){
        int lane = t;
        unsigned sup = 0u;                       // lane b owns sup word b
        int nblk = (v + 31) >> 5;
        for (int b=0; b<nblk; b++){
            unsigned sb = sblk[b];
            if (sb == 0u) continue;              // no suppressors in block
            unsigned s = __shfl_sync(FULLM, sup, b);
            if (lane == 0){
                unsigned it = sb;                // ascending row order
                while (it){
                    int l = __ffs(it) - 1; it &= it - 1u;
                    if (!((s >> l) & 1u)) s |= sm[(b*32+l)*MASKW + b];
                }
            }
            s = __shfl_sync(FULLM, s, 0);
            unsigned kept = (~s) & sb;           // kept suppressor rows
            if (lane < MASKW){
                unsigned acc = 0u, it = kept;
                while (it){
                    int l = __ffs(it) - 1; it &= it - 1u;
                    acc |= sm[(b*32+l)*MASKW + lane];
                }
                sup |= acc;
            }
        }
        // warp-aggregated append of kept keys to the per-image candidate list
        for (int base=0; base<v; base+=32){
            int tp = base + lane;
            int src = (tp < v) ? (tp>>5) : 0;
            unsigned wv = __shfl_sync(FULLM, sup, src);
            bool kp = (tp < v) && !((wv >> (tp&31)) & 1u);
            unsigned bal = __ballot_sync(FULLM, kp);
            int cnt = __popc(bal);
            int bpos = 0;
            if (lane == 0 && cnt) bpos = atomicAdd(&g_ccnt[bimg], cnt);
            bpos = __shfl_sync(FULLM, bpos, 0);
            if (kp){
                int n = g_vlist[g*NB+tp];
                unsigned kh = ~(__float_as_uint(g_psc[g*NB+tp]) | 0x80000000u);
                unsigned fidx = (unsigned)(cf*NB + n);
                int pos = bpos + __popc(bal & ((1u<<lane)-1u));
                g_ckeys[bimg*CKMAX + pos] = (((unsigned long long)kh) << 32) | fidx;
            }
        }
    }
}

// ---------------- kernel 4: top-100 — shared-resident two-level histogram select ----------------
__global__ void __launch_bounds__(512) k_topk(float* __restrict__ out, int out_size)
{
    __shared__ unsigned long long sk[CKMAX];   // 32KB
    __shared__ int hist[2048];                 // 8KB
    __shared__ unsigned long long cand[CANDC]; // 4KB
    __shared__ int ccnt, s_bin, s_prefix;
    __shared__ int warpsum[16];

    int b = blockIdx.x;
    int t = threadIdx.x;
    int lane = t & 31, wid = t >> 5;
    int K = g_ccnt[b];
    if (K > CKMAX) K = CKMAX;

    if (t==0){ ccnt=0; s_bin=-1; s_prefix=0; }
    for (int i=t;i<2048;i+=512) hist[i]=0;
    __syncthreads();

    // load keys once; level-1 histogram on key bits [53,64) == kh bits [21,32)
    for (int f=t; f<K; f+=512){
        unsigned long long key = g_ckeys[b*CKMAX + f];
        sk[f] = key;
        atomicAdd(&hist[(int)(key>>53)], 1);
    }
    __syncthreads();

    int need = K < DET ? K : DET;

    // scan 2048 bins (4/thread), find bin T crossing rank `need`
    {
        int h0=hist[t*4], h1=hist[t*4+1], h2=hist[t*4+2], h3=hist[t*4+3];
        int local = h0+h1+h2+h3;
        int x = local;
        #pragma unroll
        for (int o=1;o<32;o<<=1){ int y=__shfl_up_sync(FULLM,x,o); if (lane>=o) x+=y; }
        if (lane==31) warpsum[wid]=x;
        __syncthreads();
        if (wid==0){
            int y = (lane<16)? warpsum[lane] : 0;
            #pragma unroll
            for (int o=1;o<16;o<<=1){ int z=__shfl_up_sync(FULLM,y,o); if (lane>=o) y+=z; }
            if (lane<16) warpsum[lane]=y;
        }
        __syncthreads();
        int incl = x + ((wid>0)? warpsum[wid-1] : 0);
        int excl = incl - local;
        if (need > 0){
            int c0=excl+h0, c1=c0+h1, c2=c1+h2, c3=c2+h3;
            if (excl<need && c0>=need){ s_bin=t*4;   s_prefix=excl; }
            else if (c0<need && c1>=need){ s_bin=t*4+1; s_prefix=c0; }
            else if (c1<need && c2>=need){ s_bin=t*4+2; s_prefix=c1; }
            else if (c2<need && c3>=need){ s_bin=t*4+3; s_prefix=c2; }
        }
    }
    __syncthreads();
    int T = s_bin;
    int need2 = need - s_prefix;

    // level-2: refine inside bin T on key bits [42,53)
    __syncthreads();
    for (int i=t;i<2048;i+=512) hist[i]=0;
    __syncthreads();
    if (T >= 0){
        for (int f=t; f<K; f+=512){
            unsigned long long key = sk[f];
            if ((int)(key>>53) == T) atomicAdd(&hist[(int)((key>>42)&2047)], 1);
        }
    }
    __syncthreads();
    if (t==0) s_bin = -1;
    __syncthreads();
    {
        int h0=hist[t*4], h1=hist[t*4+1], h2=hist[t*4+2], h3=hist[t*4+3];
        int local = h0+h1+h2+h3;
        int x = local;
        #pragma unroll
        for (int o=1;o<32;o<<=1){ int y=__shfl_up_sync(FULLM,x,o); if (lane>=o) x+=y; }
        if (lane==31) warpsum[wid]=x;
        __syncthreads();
        if (wid==0){
            int y = (lane<16)? warpsum[lane] : 0;
            #pragma unroll
            for (int o=1;o<16;o<<=1){ int z=__shfl_up_sync(FULLM,y,o); if (lane>=o) y+=z; }
            if (lane<16) warpsum[lane]=y;
        }
        __syncthreads();
        int incl = x + ((wid>0)? warpsum[wid-1] : 0);
        int excl = incl - local;
        if (T >= 0 && need2 > 0){
            int c0=excl+h0, c1=c0+h1, c2=c1+h2, c3=c2+h3;
            if (excl<need2 && c0>=need2) s_bin=t*4;
            else if (c0<need2 && c1>=need2) s_bin=t*4+1;
            else if (c1<need2 && c2>=need2) s_bin=t*4+2;
            else if (c2<need2 && c3>=need2) s_bin=t*4+3;
        }
    }
    __syncthreads();
    int T2 = s_bin;

    // compact: bin<T, or bin==T && sub<=T2   (provably contains exact top-need)
    if (T >= 0){
        for (int f=t; f<K; f+=512){
            unsigned long long key = sk[f];
            int cb = (int)(key>>53);
            bool take = (cb < T) || (cb == T && T2 >= 0 && (int)((key>>42)&2047) <= T2);
            if (take){
                int p = atomicAdd(&ccnt, 1);
                if (p < CANDC) cand[p] = key;
            }
        }
    }
    __syncthreads();
    int Kc = ccnt < CANDC ? ccnt : CANDC;
    int P = 128;
    while (P < Kc) P <<= 1;
    for (int f = Kc + t; f < P; f += 512) cand[f] = 0xFFFFFFFFFFFFFFFFull;
    __syncthreads();

    for (int k=2;k<=P;k<<=1)
        for (int j=k>>1;j>0;j>>=1){
            for (int p=t;p<P;p+=512){
                int ixj = p ^ j;
                if (ixj > p){
                    unsigned long long A = cand[p], Bv = cand[ixj];
                    if ((A > Bv) == ((p & k) == 0)){ cand[p] = Bv; cand[ixj] = A; }
                }
            }
            __syncthreads();
        }

    if (t < DET){
        bool okd = (t < need) && (t < Kc);
        unsigned long long key = okd ? cand[t] : 0xFFFFFFFFFFFFFFFFull;
        float vals[6] = {0.f,0.f,0.f,0.f,0.f,0.f};
        float lab = 0.0f;
        if (okd){
            unsigned f  = (unsigned)(key & 0xFFFFFFFFull);
            unsigned ub = ~((unsigned)(key >> 32));
            float sc = __uint_as_float(ub ^ 0x80000000u);   // kept scores > 0
            int bi = b*NFG*NB + (int)f;
            #pragma unroll
            for (int kk=0;kk<5;kk++) vals[kk] = g_boxes[bi*5+kk];
            vals[5] = sc;
            lab = (float)((int)f / NB + 1);
        }
        int base = b*DET*6 + t*6;
        #pragma unroll
        for (int kk=0;kk<6;kk++) if (base+kk < out_size) out[base+kk] = vals[kk];
        int li = NIMG*DET*6 + b*DET + t;
        if (li < out_size) out[li] = lab;
    }
}

// ---------------- launcher ----------------
extern "C" void kernel_launch(void* const* d_in, const int* in_sizes, int n_in,
                              void* d_out, int out_size)
{
    const float* logits = (const float*)d_in[0];   // (768, 11)
    const float* reg    = (const float*)d_in[1];   // (768, 55)
    const float* rr     = (const float*)d_in[2];   // (768, 5)

    k_decsort<<<NGRP, 512>>>(logits, reg, rr);
    k_pairs  <<<NGRP*SUBB, 256>>>();
    k_greedy <<<NGRP, 256>>>();
    k_topk   <<<NIMG, 512>>>((float*)d_out, out_size);
}